// round 15
// baseline (speedup 1.0000x reference)
#include <cuda_runtime.h>
#include <math.h>

#define FULL 0xffffffffu
#define B_     2
#define C_     512
#define N_     4096
#define HEADS_ 8
#define DH_    64
#define KMAX_  32

typedef unsigned long long u64;

// ---------------- scratch (device globals; no allocation allowed) ----------------
__device__ float g_Q[B_ * HEADS_ * DH_ * N_];   // [b][h][d][n]  (plain)
__device__ float g_K[B_ * HEADS_ * DH_ * N_];   // [b][h][d][n]  (plain)
__device__ float g_V[B_ * HEADS_ * N_ * DH_];   // [b][h][n][d]
__device__ float g_A[B_ * C_ * N_];             // attention out, [b][c][n]
__device__ int   g_kdyn[B_ * N_];

// ---------------- helpers ----------------
__device__ __forceinline__ unsigned ordf(float v) {
    unsigned u = __float_as_uint(v);
    return (u & 0x80000000u) ? ~u : (u | 0x80000000u);
}
__device__ __forceinline__ float iordf(unsigned o) {
    unsigned u = (o & 0x80000000u) ? (o & 0x7fffffffu) : ~o;
    return __uint_as_float(u);
}
__device__ __forceinline__ u64 pk2(float lo, float hi) {
    u64 r; asm("mov.b64 %0,{%1,%2};" : "=l"(r) : "f"(lo), "f"(hi)); return r;
}
__device__ __forceinline__ void fma2(u64& d, u64 a, u64 b) {
    asm("fma.rn.f32x2 %0,%1,%2,%0;" : "+l"(d) : "l"(a), "l"(b));
}
__device__ __forceinline__ float2 upk2(u64 v) {
    float2 f; asm("mov.b64 {%0,%1},%2;" : "=f"(f.x), "=f"(f.y) : "l"(v)); return f;
}
__device__ __forceinline__ void cpa16(unsigned dst, const void* src) {
    asm volatile("cp.async.cg.shared.global [%0], [%1], 16;" :: "r"(dst), "l"(src));
}
__device__ __forceinline__ void cpa_commit() { asm volatile("cp.async.commit_group;"); }
__device__ __forceinline__ void cpa_wait0()  { asm volatile("cp.async.wait_group 0;" ::: "memory"); }

// ================= kernel 1: QKV GEMM (packed FFMA2, plain Q/K output) =========
__global__ __launch_bounds__(256) void qkv_gemm_kernel(const float* __restrict__ x,
                                                       const float* __restrict__ w) {
    __shared__ float Ws[16][68];
    __shared__ float Xs[16][132];
    __shared__ float St[64][132];
    int n0 = blockIdx.x * 128;
    int o0 = blockIdx.y * 64;
    int b  = blockIdx.z;
    int tid = threadIdx.x;
    int ty = tid >> 4, tx = tid & 15;
    const float* xb = x + b * C_ * N_;

    u64 accp[4][4];
#pragma unroll
    for (int a = 0; a < 4; a++)
#pragma unroll
        for (int c = 0; c < 4; c++) accp[a][c] = 0ull;

    for (int c0 = 0; c0 < C_; c0 += 16) {
        {   // W tile transpose-load
            int oo = tid >> 2;
            int cc4 = (tid & 3) << 2;
            float4 wv = *(const float4*)(w + (o0 + oo) * C_ + c0 + cc4);
            Ws[cc4 + 0][oo] = wv.x; Ws[cc4 + 1][oo] = wv.y;
            Ws[cc4 + 2][oo] = wv.z; Ws[cc4 + 3][oo] = wv.w;
        }
#pragma unroll
        for (int r = 0; r < 2; r++) {
            int f = tid + r * 256;
            int cc = f >> 5, n4 = (f & 31) << 2;
            *(float4*)&Xs[cc][n4] = *(const float4*)(xb + (c0 + cc) * N_ + n0 + n4);
        }
        __syncthreads();
#pragma unroll
        for (int cc = 0; cc < 16; cc++) {
            float4 wv = *(float4*)&Ws[cc][ty * 4];
            ulonglong2 xa = *(ulonglong2*)&Xs[cc][tx * 8];
            ulonglong2 xb2 = *(ulonglong2*)&Xs[cc][tx * 8 + 4];
            u64 wd[4] = {pk2(wv.x, wv.x), pk2(wv.y, wv.y), pk2(wv.z, wv.z), pk2(wv.w, wv.w)};
#pragma unroll
            for (int a = 0; a < 4; a++) {
                fma2(accp[a][0], wd[a], xa.x);
                fma2(accp[a][1], wd[a], xa.y);
                fma2(accp[a][2], wd[a], xb2.x);
                fma2(accp[a][3], wd[a], xb2.y);
            }
        }
        __syncthreads();
    }

    float acc[4][8];
#pragma unroll
    for (int a = 0; a < 4; a++)
#pragma unroll
        for (int c = 0; c < 4; c++) {
            float2 f = upk2(accp[a][c]);
            acc[a][2 * c] = f.x; acc[a][2 * c + 1] = f.y;
        }

    int sel = o0 >> 9;            // 0:Q 1:K 2:V
    int h   = (o0 & 511) >> 6;
    if (sel < 2) {
        float* dst = (sel == 0 ? g_Q : g_K) + (b * HEADS_ + h) * DH_ * N_;
#pragma unroll
        for (int a = 0; a < 4; a++) {
            int d = ty * 4 + a;
            *(float4*)(dst + d * N_ + n0 + tx * 8)     = make_float4(acc[a][0], acc[a][1], acc[a][2], acc[a][3]);
            *(float4*)(dst + d * N_ + n0 + tx * 8 + 4) = make_float4(acc[a][4], acc[a][5], acc[a][6], acc[a][7]);
        }
    } else {
#pragma unroll
        for (int a = 0; a < 4; a++)
#pragma unroll
            for (int c = 0; c < 8; c++) St[ty * 4 + a][tx * 8 + c] = acc[a][c];
        __syncthreads();
        float* dst = g_V + ((b * HEADS_ + h) * N_ + n0) * DH_;
#pragma unroll
        for (int r = 0; r < 8; r++) {
            int f = tid + r * 256;
            int nl = f >> 4, dd = (f & 15) << 2;
            float4 v = make_float4(St[dd][nl], St[dd + 1][nl], St[dd + 2][nl], St[dd + 3][nl]);
            *(float4*)(dst + nl * DH_ + dd) = v;
        }
    }
}

// ================= kernel 2: gate MLP -> k_dyn =================
__global__ __launch_bounds__(128) void gate_kernel(const float* __restrict__ x,
                                                   const float* __restrict__ w1,
                                                   const float* __restrict__ b1,
                                                   const float* __restrict__ w2,
                                                   const float* __restrict__ b2) {
    __shared__ float Xs[512][17];
    __shared__ float T1s[128][17];
    int n0 = blockIdx.x * 16;
    int b  = blockIdx.y;
    int tid = threadIdx.x;
    const float* xb = x + b * C_ * N_;
#pragma unroll 8
    for (int r = 0; r < 64; r++) {
        int f = tid + r * 128;
        int c = f >> 4, nn = f & 15;
        Xs[c][nn] = xb[c * N_ + n0 + nn];
    }
    __syncthreads();
    int nn = tid & 15, ob = tid >> 4;
    for (int rep = 0; rep < 16; rep++) {
        int o = ob + rep * 8;
        float acc = b1[o];
        const float* wr = w1 + o * 512;
        for (int c = 0; c < 512; c += 4) {
            float4 wv = *(const float4*)(wr + c);
            acc += wv.x * Xs[c][nn] + wv.y * Xs[c + 1][nn]
                 + wv.z * Xs[c + 2][nn] + wv.w * Xs[c + 3][nn];
        }
        T1s[o][nn] = fmaxf(acc, 0.f);
    }
    __syncthreads();
    {
        int p = tid >> 3;
        int seg = tid & 7;
        float s = 0.f;
        for (int o = 0; o < 16; o++) s += w2[seg * 16 + o] * T1s[seg * 16 + o][p];
#pragma unroll
        for (int o = 4; o; o >>= 1) s += __shfl_xor_sync(FULL, s, o);
        if (seg == 0) {
            s += b2[0];
            float tau = 1.f / (1.f + expf(-s));
            int kd = (int)(tau * 32.f);
            kd = kd < 4 ? 4 : (kd > 32 ? 32 : kd);
            g_kdyn[b * N_ + n0 + p] = kd;
        }
    }
}

// ================= kernel 3: fused KNN attention (query-pair packed) ===========
// 256 threads, 2 blocks/SM. Warp w owns queries w*8..w*8+7 (query-pairs in f32x2).
// K read scalar from smem (halved crossbar traffic vs d-pair packing); each
// (q,j) dot product is a single sequential fp32 chain over d (reference order).
__global__ __launch_bounds__(256, 2) void attn_kernel() {
    extern __shared__ char smraw[];
    float* Qs  = (float*)smraw;                       // [64 d][68]
    float* KTb = (float*)(smraw + 64 * 68 * 4);       // 2 x [64 d][132]
    float* Wsm = (float*)smraw;                       // alias after streaming: [64][33]
    int*   Ism = (int*)(smraw + 64 * 33 * 4);         // alias (within Q region)

    int i0 = blockIdx.x * 64;
    int h  = blockIdx.y;
    int b  = blockIdx.z;
    int tid = threadIdx.x;
    int lane = tid & 31;
    int wrp  = tid >> 5;            // 0..7
    int bh = b * HEADS_ + h;
    const float* Qg = g_Q + bh * DH_ * N_;
    const float* Kg = g_K + bh * DH_ * N_;
    const float* Vg = g_V + bh * N_ * DH_;

    int st_d  = tid >> 2;           // 0..63 (stager row)
    int st_sg = tid & 3;            // 0..3

    // ---- prologue: cp.async Q tile + K chunk 0 ----
    {
        unsigned qdst = (unsigned)__cvta_generic_to_shared(Qs + st_d * 68 + st_sg * 16);
        const float* qsrc = Qg + st_d * N_ + i0 + st_sg * 16;
#pragma unroll
        for (int t = 0; t < 4; t++) cpa16(qdst + t * 16, qsrc + t * 4);
        unsigned kdst = (unsigned)__cvta_generic_to_shared(KTb + st_d * 132 + st_sg * 32);
        const float* ksrc = Kg + st_d * N_ + st_sg * 32;
#pragma unroll
        for (int t = 0; t < 8; t++) cpa16(kdst + t * 16, ksrc + t * 4);
        cpa_commit();
    }
    cpa_wait0();
    __syncthreads();

    u64 key[8];                      // sorted ascending across lanes per query
    float thv[8];                    // value of worst kept entry
    const float* qbase = Qs + wrp * 8;

    for (int c = 0; c < 32; c++) {
        int j0 = c * 128;
        if (c + 1 < 32) {
            float* dstp = KTb + (((c + 1) & 1) ? (64 * 132) : 0) + st_d * 132 + st_sg * 32;
            unsigned dst = (unsigned)__cvta_generic_to_shared(dstp);
            const float* src = Kg + st_d * N_ + (j0 + 128) + st_sg * 32;
#pragma unroll
            for (int t = 0; t < 8; t++) cpa16(dst + t * 16, src + t * 4);
            cpa_commit();
        }

        const float* kb = KTb + ((c & 1) ? (64 * 132) : 0);

        // ---- packed score GEMM: acc2[qp][s] = (q_even, q_odd) partial scores ----
        u64 acc2[4][4];
#pragma unroll
        for (int qp = 0; qp < 4; qp++)
#pragma unroll
            for (int s = 0; s < 4; s++) acc2[qp][s] = 0ull;

#pragma unroll 8
        for (int d = 0; d < 64; d++) {
            const u64* qp_ = (const u64*)(qbase + d * 68);
            ulonglong2 q01 = *(const ulonglong2*)qp_;       // qpairs 0,1 (broadcast)
            ulonglong2 q23 = *(const ulonglong2*)(qp_ + 2); // qpairs 2,3
            const float* kr = kb + d * 132;
            float k0 = kr[lane], k1 = kr[32 + lane], k2 = kr[64 + lane], k3 = kr[96 + lane];
            u64 kd0 = pk2(k0, k0), kd1 = pk2(k1, k1), kd2 = pk2(k2, k2), kd3 = pk2(k3, k3);
            fma2(acc2[0][0], q01.x, kd0); fma2(acc2[0][1], q01.x, kd1);
            fma2(acc2[0][2], q01.x, kd2); fma2(acc2[0][3], q01.x, kd3);
            fma2(acc2[1][0], q01.y, kd0); fma2(acc2[1][1], q01.y, kd1);
            fma2(acc2[1][2], q01.y, kd2); fma2(acc2[1][3], q01.y, kd3);
            fma2(acc2[2][0], q23.x, kd0); fma2(acc2[2][1], q23.x, kd1);
            fma2(acc2[2][2], q23.x, kd2); fma2(acc2[2][3], q23.x, kd3);
            fma2(acc2[3][0], q23.y, kd0); fma2(acc2[3][1], q23.y, kd1);
            fma2(acc2[3][2], q23.y, kd2); fma2(acc2[3][3], q23.y, kd3);
        }

        float sc[8][4];
#pragma unroll
        for (int qp = 0; qp < 4; qp++)
#pragma unroll
            for (int s = 0; s < 4; s++) {
                float2 f = upk2(acc2[qp][s]);
                sc[2 * qp][s]     = f.x;     // score for j = j0 + s*32 + lane
                sc[2 * qp + 1][s] = f.y;
            }

        if (c == 0) {
            // init sorted list from slot 0 (j = lane)
#pragma unroll
            for (int q = 0; q < 8; q++) {
                u64 k0 = ((u64)(~ordf(sc[q][0])) << 32) | (unsigned)lane;
#pragma unroll
                for (int kk = 2; kk <= 32; kk <<= 1) {
#pragma unroll
                    for (int j = kk >> 1; j > 0; j >>= 1) {
                        u64 partner = __shfl_xor_sync(FULL, k0, j);
                        bool dirAsc = ((lane & kk) == 0);
                        bool lower  = ((lane & j) == 0);
                        u64 mn = k0 < partner ? k0 : partner;
                        u64 mx = k0 < partner ? partner : k0;
                        k0 = (lower == dirAsc) ? mn : mx;
                    }
                }
                key[q] = k0;
                u64 k31 = __shfl_sync(FULL, k0, 31);
                thv[q] = iordf(~(unsigned)(k31 >> 32));
                sc[q][0] = -INFINITY;
            }
        }

        // ---- streaming insert (sorted-list shift) ----
#pragma unroll
        for (int q = 0; q < 8; q++) {
#pragma unroll
            for (int s = 0; s < 4; s++) {
                unsigned m = __ballot_sync(FULL, sc[q][s] > thv[q]);
                while (m) {
                    int src = __ffs(m) - 1; m &= m - 1;
                    float v = __shfl_sync(FULL, sc[q][s], src);
                    if (v > thv[q]) {       // warp-uniform
                        u64 cnd = ((u64)(~ordf(v)) << 32)
                                | (unsigned)(j0 + (s << 5) + src);
                        unsigned below = __ballot_sync(FULL, key[q] < cnd);
                        int pos = __popc(below);
                        u64 sh = __shfl_up_sync(FULL, key[q], 1);
                        key[q] = (lane < pos) ? key[q] : (lane == pos ? cnd : sh);
                        u64 k31 = __shfl_sync(FULL, key[q], 31);
                        thv[q] = iordf(~(unsigned)(k31 >> 32));
                    }
                }
            }
        }

        cpa_wait0();
        __syncthreads();
    }

    // ---- finalize: list already sorted (value desc, idx asc) ----
    int kd8[8];
#pragma unroll
    for (int q = 0; q < 8; q++) kd8[q] = g_kdyn[b * N_ + i0 + wrp * 8 + q];

#pragma unroll
    for (int q = 0; q < 8; q++) {
        int il = wrp * 8 + q;
        float val = iordf(~(unsigned)(key[q] >> 32));
        int   idx = (int)(key[q] & 0xffffffffull);

        int kd = kd8[q];
        float sv = val * 0.125f;                    // 1/sqrt(64)
        float mx = __shfl_sync(FULL, sv, 0);        // rank-0 = max
        float e  = (lane < kd) ? expf(sv - mx) : 0.f;
        float ssum = e;
#pragma unroll
        for (int o = 16; o; o >>= 1) ssum += __shfl_xor_sync(FULL, ssum, o);
        float wt = e / ssum;

        Wsm[il * 33 + lane] = wt;
        Ism[il * 33 + lane] = idx;
    }
    __syncthreads();

    // ---- gather: thread = (i = tid&63, dq = tid>>6 -> 16 d's) ----
    {
        int i  = tid & 63;
        int dq = tid >> 6;              // 0..3
        const float* Wr = &Wsm[i * 33];
        const int*   Ir = &Ism[i * 33];
        float4 o0 = make_float4(0.f, 0.f, 0.f, 0.f);
        float4 o1 = make_float4(0.f, 0.f, 0.f, 0.f);
        float4 o2 = make_float4(0.f, 0.f, 0.f, 0.f);
        float4 o3 = make_float4(0.f, 0.f, 0.f, 0.f);
#pragma unroll 4
        for (int k = 0; k < 32; k++) {
            float wv = Wr[k];
            int   ix = Ir[k];
            const float* vrow = Vg + ix * DH_ + dq * 16;
            float4 a = *(const float4*)(vrow);
            float4 bb = *(const float4*)(vrow + 4);
            float4 cc = *(const float4*)(vrow + 8);
            float4 dd = *(const float4*)(vrow + 12);
            o0.x += wv * a.x;  o0.y += wv * a.y;  o0.z += wv * a.z;  o0.w += wv * a.w;
            o1.x += wv * bb.x; o1.y += wv * bb.y; o1.z += wv * bb.z; o1.w += wv * bb.w;
            o2.x += wv * cc.x; o2.y += wv * cc.y; o2.z += wv * cc.z; o2.w += wv * cc.w;
            o3.x += wv * dd.x; o3.y += wv * dd.y; o3.z += wv * dd.z; o3.w += wv * dd.w;
        }
        float* Ab = g_A + (b * C_ + h * 64) * N_ + i0 + i;
        float ov[16] = {o0.x, o0.y, o0.z, o0.w, o1.x, o1.y, o1.z, o1.w,
                        o2.x, o2.y, o2.z, o2.w, o3.x, o3.y, o3.z, o3.w};
#pragma unroll
        for (int s = 0; s < 16; s++) {
            int d = dq * 16 + s;
            Ab[d * N_] = ov[s];
        }
    }
}

// ================= kernel 4: proj GEMM + bias + residual (packed FFMA2) =================
__global__ __launch_bounds__(256) void proj_kernel(const float* __restrict__ x,
                                                   const float* __restrict__ w,
                                                   const float* __restrict__ bias,
                                                   float* __restrict__ out) {
    __shared__ float Ws[16][68];
    __shared__ float As[16][132];
    int n0 = blockIdx.x * 128;
    int o0 = blockIdx.y * 64;
    int b  = blockIdx.z;
    int tid = threadIdx.x;
    int ty = tid >> 4, tx = tid & 15;
    const float* Ab = g_A + b * C_ * N_;

    u64 accp[4][4];
#pragma unroll
    for (int a = 0; a < 4; a++)
#pragma unroll
        for (int c = 0; c < 4; c++) accp[a][c] = 0ull;

    for (int c0 = 0; c0 < C_; c0 += 16) {
        {
            int oo = tid >> 2;
            int cc4 = (tid & 3) << 2;
            float4 wv = *(const float4*)(w + (o0 + oo) * C_ + c0 + cc4);
            Ws[cc4 + 0][oo] = wv.x; Ws[cc4 + 1][oo] = wv.y;
            Ws[cc4 + 2][oo] = wv.z; Ws[cc4 + 3][oo] = wv.w;
        }
#pragma unroll
        for (int r = 0; r < 2; r++) {
            int f = tid + r * 256;
            int cc = f >> 5, n4 = (f & 31) << 2;
            *(float4*)&As[cc][n4] = *(const float4*)(Ab + (c0 + cc) * N_ + n0 + n4);
        }
        __syncthreads();
#pragma unroll
        for (int cc = 0; cc < 16; cc++) {
            float4 wv = *(float4*)&Ws[cc][ty * 4];
            ulonglong2 xa = *(ulonglong2*)&As[cc][tx * 8];
            ulonglong2 xb2 = *(ulonglong2*)&As[cc][tx * 8 + 4];
            u64 wd[4] = {pk2(wv.x, wv.x), pk2(wv.y, wv.y), pk2(wv.z, wv.z), pk2(wv.w, wv.w)};
#pragma unroll
            for (int a = 0; a < 4; a++) {
                fma2(accp[a][0], wd[a], xa.x);
                fma2(accp[a][1], wd[a], xa.y);
                fma2(accp[a][2], wd[a], xb2.x);
                fma2(accp[a][3], wd[a], xb2.y);
            }
        }
        __syncthreads();
    }

    const float* xb = x + b * C_ * N_;
    float* ob = out + b * C_ * N_;
#pragma unroll
    for (int a = 0; a < 4; a++) {
        int o = o0 + ty * 4 + a;
        float bs = bias[o];
        float2 p0 = upk2(accp[a][0]);
        float2 p1 = upk2(accp[a][1]);
        float2 p2 = upk2(accp[a][2]);
        float2 p3 = upk2(accp[a][3]);
        float4 x0 = *(const float4*)(xb + o * N_ + n0 + tx * 8);
        float4 x1 = *(const float4*)(xb + o * N_ + n0 + tx * 8 + 4);
        float4 r0 = make_float4(x0.x + bs + p0.x, x0.y + bs + p0.y,
                                x0.z + bs + p1.x, x0.w + bs + p1.y);
        float4 r1 = make_float4(x1.x + bs + p2.x, x1.y + bs + p2.y,
                                x1.z + bs + p3.x, x1.w + bs + p3.y);
        *(float4*)(ob + o * N_ + n0 + tx * 8)     = r0;
        *(float4*)(ob + o * N_ + n0 + tx * 8 + 4) = r1;
    }
}

// ================= launch =================
extern "C" void kernel_launch(void* const* d_in, const int* in_sizes, int n_in,
                              void* d_out, int out_size) {
    const float* x      = (const float*)d_in[0];
    const float* w_qkv  = (const float*)d_in[1];
    const float* w_proj = (const float*)d_in[2];
    const float* b_proj = (const float*)d_in[3];
    const float* w_g1   = (const float*)d_in[4];
    const float* b_g1   = (const float*)d_in[5];
    const float* w_g2   = (const float*)d_in[6];
    const float* b_g2   = (const float*)d_in[7];
    float* out = (float*)d_out;

    qkv_gemm_kernel<<<dim3(N_ / 128, (3 * C_) / 64, B_), 256>>>(x, w_qkv);
    gate_kernel<<<dim3(N_ / 16, B_), 128>>>(x, w_g1, b_g1, w_g2, b_g2);

    const int attn_smem = (64 * 68 + 2 * 64 * 132) * 4;   // 84992 B
    cudaFuncSetAttribute(attn_kernel, cudaFuncAttributeMaxDynamicSharedMemorySize, attn_smem);
    attn_kernel<<<dim3(N_ / 64, HEADS_, B_), 256, attn_smem>>>();

    proj_kernel<<<dim3(N_ / 128, C_ / 64, B_), 256>>>(x, w_proj, b_proj, out);
}

// round 16
// speedup vs baseline: 1.0441x; 1.0441x over previous
#include <cuda_runtime.h>
#include <math.h>

#define FULL 0xffffffffu
#define B_     2
#define C_     512
#define N_     4096
#define HEADS_ 8
#define DH_    64
#define KMAX_  32

typedef unsigned long long u64;

// ---------------- scratch (device globals; no allocation allowed) ----------------
// Q,K stored d-pair interleaved: float2 rows [b][h][d2][n], d2 = d/2
__device__ float g_Q[B_ * HEADS_ * DH_ * N_];
__device__ float g_K[B_ * HEADS_ * DH_ * N_];
__device__ float g_V[B_ * HEADS_ * N_ * DH_];   // [b][h][n][d]
__device__ float g_A[B_ * C_ * N_];             // attention out, [b][c][n]
__device__ int   g_kdyn[B_ * N_];

// ---------------- helpers ----------------
__device__ __forceinline__ unsigned ordf(float v) {
    unsigned u = __float_as_uint(v);
    return (u & 0x80000000u) ? ~u : (u | 0x80000000u);
}
__device__ __forceinline__ float iordf(unsigned o) {
    unsigned u = (o & 0x80000000u) ? (o & 0x7fffffffu) : ~o;
    return __uint_as_float(u);
}
__device__ __forceinline__ u64 pk2(float lo, float hi) {
    u64 r; asm("mov.b64 %0,{%1,%2};" : "=l"(r) : "f"(lo), "f"(hi)); return r;
}
__device__ __forceinline__ void fma2(u64& d, u64 a, u64 b) {
    asm("fma.rn.f32x2 %0,%1,%2,%0;" : "+l"(d) : "l"(a), "l"(b));
}
__device__ __forceinline__ float2 upk2(u64 v) {
    float2 f; asm("mov.b64 {%0,%1},%2;" : "=f"(f.x), "=f"(f.y) : "l"(v)); return f;
}
__device__ __forceinline__ void cpa16(unsigned dst, const void* src) {
    asm volatile("cp.async.cg.shared.global [%0], [%1], 16;" :: "r"(dst), "l"(src));
}
__device__ __forceinline__ void cpa_commit() { asm volatile("cp.async.commit_group;"); }
__device__ __forceinline__ void cpa_wait0()  { asm volatile("cp.async.wait_group 0;" ::: "memory"); }

// ================= kernel 1: QKV GEMM (packed FFMA2, interleaved Q/K output) ====
__global__ __launch_bounds__(256) void qkv_gemm_kernel(const float* __restrict__ x,
                                                       const float* __restrict__ w) {
    __shared__ float Ws[16][68];
    __shared__ float Xs[16][132];
    __shared__ float St[64][132];
    int n0 = blockIdx.x * 128;
    int o0 = blockIdx.y * 64;
    int b  = blockIdx.z;
    int tid = threadIdx.x;
    int ty = tid >> 4, tx = tid & 15;
    const float* xb = x + b * C_ * N_;

    u64 accp[4][4];
#pragma unroll
    for (int a = 0; a < 4; a++)
#pragma unroll
        for (int c = 0; c < 4; c++) accp[a][c] = 0ull;

    for (int c0 = 0; c0 < C_; c0 += 16) {
        {   // W tile transpose-load
            int oo = tid >> 2;
            int cc4 = (tid & 3) << 2;
            float4 wv = *(const float4*)(w + (o0 + oo) * C_ + c0 + cc4);
            Ws[cc4 + 0][oo] = wv.x; Ws[cc4 + 1][oo] = wv.y;
            Ws[cc4 + 2][oo] = wv.z; Ws[cc4 + 3][oo] = wv.w;
        }
#pragma unroll
        for (int r = 0; r < 2; r++) {
            int f = tid + r * 256;
            int cc = f >> 5, n4 = (f & 31) << 2;
            *(float4*)&Xs[cc][n4] = *(const float4*)(xb + (c0 + cc) * N_ + n0 + n4);
        }
        __syncthreads();
#pragma unroll
        for (int cc = 0; cc < 16; cc++) {
            float4 wv = *(float4*)&Ws[cc][ty * 4];
            ulonglong2 xa = *(ulonglong2*)&Xs[cc][tx * 8];
            ulonglong2 xb2 = *(ulonglong2*)&Xs[cc][tx * 8 + 4];
            u64 wd[4] = {pk2(wv.x, wv.x), pk2(wv.y, wv.y), pk2(wv.z, wv.z), pk2(wv.w, wv.w)};
#pragma unroll
            for (int a = 0; a < 4; a++) {
                fma2(accp[a][0], wd[a], xa.x);
                fma2(accp[a][1], wd[a], xa.y);
                fma2(accp[a][2], wd[a], xb2.x);
                fma2(accp[a][3], wd[a], xb2.y);
            }
        }
        __syncthreads();
    }

    float acc[4][8];
#pragma unroll
    for (int a = 0; a < 4; a++)
#pragma unroll
        for (int c = 0; c < 4; c++) {
            float2 f = upk2(accp[a][c]);
            acc[a][2 * c] = f.x; acc[a][2 * c + 1] = f.y;
        }

    int sel = o0 >> 9;            // 0:Q 1:K 2:V
    int h   = (o0 & 511) >> 6;
    if (sel < 2) {
        // interleaved write: row d2 = d/2, float2 = (d even, d odd)
        float2* dst = (float2*)((sel == 0 ? g_Q : g_K) + (b * HEADS_ + h) * DH_ * N_);
#pragma unroll
        for (int a = 0; a < 4; a += 2) {
            int d2 = ty * 2 + (a >> 1);
            float2* d2p = dst + d2 * N_ + n0 + tx * 8;
#pragma unroll
            for (int c = 0; c < 8; c += 2) {
                *(float4*)&d2p[c] = make_float4(acc[a][c], acc[a + 1][c],
                                                acc[a][c + 1], acc[a + 1][c + 1]);
            }
        }
    } else {
#pragma unroll
        for (int a = 0; a < 4; a++)
#pragma unroll
            for (int c = 0; c < 8; c++) St[ty * 4 + a][tx * 8 + c] = acc[a][c];
        __syncthreads();
        float* dst = g_V + ((b * HEADS_ + h) * N_ + n0) * DH_;
#pragma unroll
        for (int r = 0; r < 8; r++) {
            int f = tid + r * 256;
            int nl = f >> 4, dd = (f & 15) << 2;
            float4 v = make_float4(St[dd][nl], St[dd + 1][nl], St[dd + 2][nl], St[dd + 3][nl]);
            *(float4*)(dst + nl * DH_ + dd) = v;
        }
    }
}

// ================= kernel 2: gate MLP -> k_dyn =================
__global__ __launch_bounds__(128) void gate_kernel(const float* __restrict__ x,
                                                   const float* __restrict__ w1,
                                                   const float* __restrict__ b1,
                                                   const float* __restrict__ w2,
                                                   const float* __restrict__ b2) {
    __shared__ float Xs[512][17];
    __shared__ float T1s[128][17];
    int n0 = blockIdx.x * 16;
    int b  = blockIdx.y;
    int tid = threadIdx.x;
    const float* xb = x + b * C_ * N_;
#pragma unroll 8
    for (int r = 0; r < 64; r++) {
        int f = tid + r * 128;
        int c = f >> 4, nn = f & 15;
        Xs[c][nn] = xb[c * N_ + n0 + nn];
    }
    __syncthreads();
    int nn = tid & 15, ob = tid >> 4;
    for (int rep = 0; rep < 16; rep++) {
        int o = ob + rep * 8;
        float acc = b1[o];
        const float* wr = w1 + o * 512;
        for (int c = 0; c < 512; c += 4) {
            float4 wv = *(const float4*)(wr + c);
            acc += wv.x * Xs[c][nn] + wv.y * Xs[c + 1][nn]
                 + wv.z * Xs[c + 2][nn] + wv.w * Xs[c + 3][nn];
        }
        T1s[o][nn] = fmaxf(acc, 0.f);
    }
    __syncthreads();
    {
        int p = tid >> 3;
        int seg = tid & 7;
        float s = 0.f;
        for (int o = 0; o < 16; o++) s += w2[seg * 16 + o] * T1s[seg * 16 + o][p];
#pragma unroll
        for (int o = 4; o; o >>= 1) s += __shfl_xor_sync(FULL, s, o);
        if (seg == 0) {
            s += b2[0];
            float tau = 1.f / (1.f + expf(-s));
            int kd = (int)(tau * 32.f);
            kd = kd < 4 ? 4 : (kd > 32 ? 32 : kd);
            g_kdyn[b * N_ + n0 + p] = kd;
        }
    }
}

// ================= kernel 3: fused KNN attention (R11 + lmax pre-check) ========
__global__ __launch_bounds__(512, 2) void attn_kernel() {
    extern __shared__ char smraw[];
    float2* Q2  = (float2*)smraw;                      // [32 d2][66]
    float2* KTb = (float2*)(smraw + 32 * 66 * 8);      // 2 x [32 d2][132]
    float*  Wsm = (float*)smraw;                       // alias after streaming: [64][33]
    int*    Ism = (int*)(smraw + 64 * 33 * 4);         // alias: [64][33]

    int i0 = blockIdx.x * 64;
    int h  = blockIdx.y;
    int b  = blockIdx.z;
    int tid = threadIdx.x;
    int lane = tid & 31;
    int wrp  = tid >> 5;            // 0..15
    int bh = b * HEADS_ + h;
    const float2* Qg2 = (const float2*)(g_Q + bh * DH_ * N_);
    const float2* Kg2 = (const float2*)(g_K + bh * DH_ * N_);
    const float*  Vg  = g_V + bh * N_ * DH_;

    int st_d2  = tid >> 4;          // 0..31
    int st_seg = tid & 15;          // 0..15

    // ---- load Q tile (straight copy, layout already interleaved) ----
#pragma unroll
    for (int r = 0; r < 2; r++) {
        int f = tid + r * 512;
        int d2 = f >> 5, c4 = (f & 31) << 1;
        *(float4*)&Q2[d2 * 66 + c4] = *(const float4*)(Qg2 + d2 * N_ + i0 + c4);
    }

    // ---- prologue: cp.async K chunk 0 -> buf0 ----
    {
        unsigned dst = (unsigned)__cvta_generic_to_shared(KTb + st_d2 * 132 + st_seg * 8);
        const float2* src = Kg2 + st_d2 * N_ + st_seg * 8;
#pragma unroll
        for (int t = 0; t < 4; t++) cpa16(dst + t * 16, src + t * 2);
        cpa_commit();
    }
    cpa_wait0();
    __syncthreads();

    u64 key[4];
    float thv[4];
    const float2* qbase = Q2 + wrp * 4;

    for (int c = 0; c < 32; c++) {
        int j0 = c * 128;
        if (c + 1 < 32) {
            float2* dstp = KTb + (((c + 1) & 1) ? (32 * 132) : 0) + st_d2 * 132 + st_seg * 8;
            unsigned dst = (unsigned)__cvta_generic_to_shared(dstp);
            const float2* src = Kg2 + st_d2 * N_ + (j0 + 128) + st_seg * 8;
#pragma unroll
            for (int t = 0; t < 4; t++) cpa16(dst + t * 16, src + t * 2);
            cpa_commit();
        }

        const float2* kb = KTb + ((c & 1) ? (32 * 132) : 0);

        // ---- packed score GEMM ----
        u64 acc2[4][4];
#pragma unroll
        for (int q = 0; q < 4; q++)
#pragma unroll
            for (int s = 0; s < 4; s++) acc2[q][s] = 0ull;

#pragma unroll 8
        for (int d2 = 0; d2 < 32; d2++) {
            const u64* qp = (const u64*)(qbase + d2 * 66);
            ulonglong2 q01 = *(const ulonglong2*)qp;
            ulonglong2 q23 = *(const ulonglong2*)(qp + 2);
            const u64* kp = (const u64*)(kb + d2 * 132) + lane;
            u64 b0 = kp[0], b1 = kp[32], b2 = kp[64], b3 = kp[96];
            fma2(acc2[0][0], q01.x, b0); fma2(acc2[0][1], q01.x, b1);
            fma2(acc2[0][2], q01.x, b2); fma2(acc2[0][3], q01.x, b3);
            fma2(acc2[1][0], q01.y, b0); fma2(acc2[1][1], q01.y, b1);
            fma2(acc2[1][2], q01.y, b2); fma2(acc2[1][3], q01.y, b3);
            fma2(acc2[2][0], q23.x, b0); fma2(acc2[2][1], q23.x, b1);
            fma2(acc2[2][2], q23.x, b2); fma2(acc2[2][3], q23.x, b3);
            fma2(acc2[3][0], q23.y, b0); fma2(acc2[3][1], q23.y, b1);
            fma2(acc2[3][2], q23.y, b2); fma2(acc2[3][3], q23.y, b3);
        }

        float sc[4][4];
#pragma unroll
        for (int q = 0; q < 4; q++)
#pragma unroll
            for (int s = 0; s < 4; s++) {
                float2 f = upk2(acc2[q][s]);
                sc[q][s] = f.x + f.y;       // score for j = j0 + s*32 + lane
            }

        if (c == 0) {
            // init sorted list from slot 0 (j = lane)
#pragma unroll
            for (int q = 0; q < 4; q++) {
                u64 k0 = ((u64)(~ordf(sc[q][0])) << 32) | (unsigned)lane;
#pragma unroll
                for (int kk = 2; kk <= 32; kk <<= 1) {
#pragma unroll
                    for (int j = kk >> 1; j > 0; j >>= 1) {
                        u64 partner = __shfl_xor_sync(FULL, k0, j);
                        bool dirAsc = ((lane & kk) == 0);
                        bool lower  = ((lane & j) == 0);
                        u64 mn = k0 < partner ? k0 : partner;
                        u64 mx = k0 < partner ? partner : k0;
                        k0 = (lower == dirAsc) ? mn : mx;
                    }
                }
                key[q] = k0;
                u64 k31 = __shfl_sync(FULL, k0, 31);
                thv[q] = iordf(~(unsigned)(k31 >> 32));
                sc[q][0] = -INFINITY;
            }
        }

        // ---- streaming insert: single lmax ballot per query, then sorted-list shift ----
#pragma unroll
        for (int q = 0; q < 4; q++) {
            float lmax = fmaxf(fmaxf(sc[q][0], sc[q][1]), fmaxf(sc[q][2], sc[q][3]));
            unsigned m = __ballot_sync(FULL, lmax > thv[q]);
            while (m) {
                int src = __ffs(m) - 1; m &= m - 1;
                float v0 = __shfl_sync(FULL, sc[q][0], src);
                float v1 = __shfl_sync(FULL, sc[q][1], src);
                float v2 = __shfl_sync(FULL, sc[q][2], src);
                float v3 = __shfl_sync(FULL, sc[q][3], src);
                float vs[4] = {v0, v1, v2, v3};
#pragma unroll
                for (int s = 0; s < 4; s++) {
                    float v = vs[s];
                    if (v > thv[q]) {       // warp-uniform (v broadcast, thv uniform)
                        u64 cnd = ((u64)(~ordf(v)) << 32)
                                | (unsigned)(j0 + (s << 5) + src);
                        unsigned below = __ballot_sync(FULL, key[q] < cnd);
                        int pos = __popc(below);
                        u64 sh = __shfl_up_sync(FULL, key[q], 1);
                        key[q] = (lane < pos) ? key[q] : (lane == pos ? cnd : sh);
                        u64 k31 = __shfl_sync(FULL, key[q], 31);
                        thv[q] = iordf(~(unsigned)(k31 >> 32));
                    }
                }
            }
        }

        cpa_wait0();
        __syncthreads();
    }

    // ---- finalize: list already sorted (value desc, idx asc) ----
    int kd4[4];
#pragma unroll
    for (int q = 0; q < 4; q++) kd4[q] = g_kdyn[b * N_ + i0 + wrp * 4 + q];

#pragma unroll
    for (int q = 0; q < 4; q++) {
        int il = wrp * 4 + q;
        float val = iordf(~(unsigned)(key[q] >> 32));
        int   idx = (int)(key[q] & 0xffffffffull);

        int kd = kd4[q];
        float sv = val * 0.125f;                    // 1/sqrt(64)
        float mx = __shfl_sync(FULL, sv, 0);        // rank-0 = max
        float e  = (lane < kd) ? expf(sv - mx) : 0.f;
        float ssum = e;
#pragma unroll
        for (int o = 16; o; o >>= 1) ssum += __shfl_xor_sync(FULL, ssum, o);
        float wt = e / ssum;

        Wsm[il * 33 + lane] = wt;
        Ism[il * 33 + lane] = idx;
    }
    __syncthreads();

    // ---- gather: thread = (i = tid&63, dq = tid>>6 -> 8 d's) ----
    {
        int i  = tid & 63;
        int dq = tid >> 6;
        const float* Wr = &Wsm[i * 33];
        const int*   Ir = &Ism[i * 33];
        float4 o0 = make_float4(0.f, 0.f, 0.f, 0.f);
        float4 o1 = make_float4(0.f, 0.f, 0.f, 0.f);
#pragma unroll 4
        for (int k = 0; k < 32; k++) {
            float wv = Wr[k];
            int   ix = Ir[k];
            const float* vrow = Vg + ix * DH_ + dq * 8;
            float4 a = *(const float4*)(vrow);
            float4 cc = *(const float4*)(vrow + 4);
            o0.x += wv * a.x;  o0.y += wv * a.y;  o0.z += wv * a.z;  o0.w += wv * a.w;
            o1.x += wv * cc.x; o1.y += wv * cc.y; o1.z += wv * cc.z; o1.w += wv * cc.w;
        }
        float* Ab = g_A + (b * C_ + h * 64) * N_ + i0 + i;
        float ov[8] = {o0.x, o0.y, o0.z, o0.w, o1.x, o1.y, o1.z, o1.w};
#pragma unroll
        for (int s = 0; s < 8; s++) {
            int d = dq * 8 + s;
            Ab[d * N_] = ov[s];
        }
    }
}

// ================= kernel 4: proj GEMM 128x128 tile, 8x8 micro (FFMA2) =========
__global__ __launch_bounds__(256) void proj_kernel(const float* __restrict__ x,
                                                   const float* __restrict__ w,
                                                   const float* __restrict__ bias,
                                                   float* __restrict__ out) {
    __shared__ float Ws[16][136];
    __shared__ float As[16][136];
    int n0 = blockIdx.x * 128;
    int o0 = blockIdx.y * 128;
    int b  = blockIdx.z;
    int tid = threadIdx.x;
    int ty = tid >> 4, tx = tid & 15;
    const float* Ab = g_A + b * C_ * N_;

    u64 accp[8][4];
#pragma unroll
    for (int a = 0; a < 8; a++)
#pragma unroll
        for (int c = 0; c < 4; c++) accp[a][c] = 0ull;

    for (int c0 = 0; c0 < C_; c0 += 16) {
        {   // W tile transpose-load: Ws[cc][oo], 128 o's x 16 cc
            int oo = tid >> 1;
            int cc0 = (tid & 1) * 8;
            const float* wr = w + (o0 + oo) * C_ + c0 + cc0;
            float4 w0 = *(const float4*)(wr);
            float4 w1 = *(const float4*)(wr + 4);
            Ws[cc0 + 0][oo] = w0.x; Ws[cc0 + 1][oo] = w0.y;
            Ws[cc0 + 2][oo] = w0.z; Ws[cc0 + 3][oo] = w0.w;
            Ws[cc0 + 4][oo] = w1.x; Ws[cc0 + 5][oo] = w1.y;
            Ws[cc0 + 6][oo] = w1.z; Ws[cc0 + 7][oo] = w1.w;
        }
        {   // A tile: As[cc][n], 16 cc x 128 n
            int cc = tid >> 4, n8 = (tid & 15) * 8;
            const float* ar = Ab + (c0 + cc) * N_ + n0 + n8;
            *(float4*)&As[cc][n8]     = *(const float4*)(ar);
            *(float4*)&As[cc][n8 + 4] = *(const float4*)(ar + 4);
        }
        __syncthreads();
#pragma unroll
        for (int cc = 0; cc < 16; cc++) {
            float4 wv0 = *(float4*)&Ws[cc][ty * 8];
            float4 wv1 = *(float4*)&Ws[cc][ty * 8 + 4];
            ulonglong2 xa = *(ulonglong2*)&As[cc][tx * 8];
            ulonglong2 xb2 = *(ulonglong2*)&As[cc][tx * 8 + 4];
            u64 wd[8] = {pk2(wv0.x, wv0.x), pk2(wv0.y, wv0.y), pk2(wv0.z, wv0.z), pk2(wv0.w, wv0.w),
                         pk2(wv1.x, wv1.x), pk2(wv1.y, wv1.y), pk2(wv1.z, wv1.z), pk2(wv1.w, wv1.w)};
#pragma unroll
            for (int a = 0; a < 8; a++) {
                fma2(accp[a][0], wd[a], xa.x);
                fma2(accp[a][1], wd[a], xa.y);
                fma2(accp[a][2], wd[a], xb2.x);
                fma2(accp[a][3], wd[a], xb2.y);
            }
        }
        __syncthreads();
    }

    const float* xb = x + b * C_ * N_;
    float* ob = out + b * C_ * N_;
#pragma unroll
    for (int a = 0; a < 8; a++) {
        int o = o0 + ty * 8 + a;
        float bs = bias[o];
        float2 p0 = upk2(accp[a][0]);
        float2 p1 = upk2(accp[a][1]);
        float2 p2 = upk2(accp[a][2]);
        float2 p3 = upk2(accp[a][3]);
        float4 x0 = *(const float4*)(xb + o * N_ + n0 + tx * 8);
        float4 x1 = *(const float4*)(xb + o * N_ + n0 + tx * 8 + 4);
        float4 r0 = make_float4(x0.x + bs + p0.x, x0.y + bs + p0.y,
                                x0.z + bs + p1.x, x0.w + bs + p1.y);
        float4 r1 = make_float4(x1.x + bs + p2.x, x1.y + bs + p2.y,
                                x1.z + bs + p3.x, x1.w + bs + p3.y);
        *(float4*)(ob + o * N_ + n0 + tx * 8)     = r0;
        *(float4*)(ob + o * N_ + n0 + tx * 8 + 4) = r1;
    }
}

// ================= launch =================
extern "C" void kernel_launch(void* const* d_in, const int* in_sizes, int n_in,
                              void* d_out, int out_size) {
    const float* x      = (const float*)d_in[0];
    const float* w_qkv  = (const float*)d_in[1];
    const float* w_proj = (const float*)d_in[2];
    const float* b_proj = (const float*)d_in[3];
    const float* w_g1   = (const float*)d_in[4];
    const float* b_g1   = (const float*)d_in[5];
    const float* w_g2   = (const float*)d_in[6];
    const float* b_g2   = (const float*)d_in[7];
    float* out = (float*)d_out;

    qkv_gemm_kernel<<<dim3(N_ / 128, (3 * C_) / 64, B_), 256>>>(x, w_qkv);
    gate_kernel<<<dim3(N_ / 16, B_), 128>>>(x, w_g1, b_g1, w_g2, b_g2);

    const int attn_smem = (32 * 66 + 2 * 32 * 132) * 8;   // 84480 B
    cudaFuncSetAttribute(attn_kernel, cudaFuncAttributeMaxDynamicSharedMemorySize, attn_smem);
    attn_kernel<<<dim3(N_ / 64, HEADS_, B_), 512, attn_smem>>>();

    proj_kernel<<<dim3(N_ / 128, C_ / 128, B_), 256>>>(x, w_proj, b_proj, out);
}